// round 7
// baseline (speedup 1.0000x reference)
#include <cuda_runtime.h>
#include <cuda_bf16.h>
#include <math.h>

// Problem constants (fixed by the reference setup_inputs)
#define BB 1024
#define AA 64
#define DD 1024
#define D4 (DD / 4)        // 256 float4 per row
#define EPS 1e-8f

// Device-global accumulators (no allocation allowed). Zero-initialized at
// module load; the last-arriving CTA resets them after finalizing, so every
// graph replay starts from the same state.
__device__ float        g_kl_sum;
__device__ float        g_ndcg_sum;
__device__ unsigned int g_done_count;

__device__ __forceinline__ float warp_sum(float v) {
    #pragma unroll
    for (int o = 16; o > 0; o >>= 1) v += __shfl_xor_sync(0xFFFFFFFFu, v, o);
    return v;
}
__device__ __forceinline__ float warp_max(float v) {
    #pragma unroll
    for (int o = 16; o > 0; o >>= 1) v = fmaxf(v, __shfl_xor_sync(0xFFFFFFFFu, v, o));
    return v;
}

__global__ __launch_bounds__(512, 2)
void listwise_kernel(const float* __restrict__ q,
                     const float* __restrict__ a_emb,
                     const float* __restrict__ scores,
                     float* __restrict__ out,
                     int out_size) {
    const int b    = blockIdx.x;
    const int tid  = threadIdx.x;
    const int warp = tid >> 5;
    const int lane = tid & 31;

    __shared__ float s_sim[AA];
    __shared__ float s_sc[AA];

    if (tid < AA) s_sc[tid] = scores[(size_t)b * AA + tid];

    // Each warp handles answers {warp, warp+16, warp+32, warp+48}.
    // q is read straight from global per iteration: the 16 warps of this CTA
    // hit the same 4 KB row -> first touch DRAM, rest L1. No startup barrier,
    // so a_emb streaming begins immediately.
    const float4* q4 = reinterpret_cast<const float4*>(q + (size_t)b * DD);
    const float4* Ab = reinterpret_cast<const float4*>(a_emb) + (size_t)b * AA * D4;

    float acc0 = 0.f, acc1 = 0.f, acc2 = 0.f, acc3 = 0.f;

    #pragma unroll
    for (int it = 0; it < 8; it++) {
        const int off = it * 32 + lane;
        float4 v0 = Ab[(size_t)(warp +  0) * D4 + off];
        float4 v1 = Ab[(size_t)(warp + 16) * D4 + off];
        float4 v2 = Ab[(size_t)(warp + 32) * D4 + off];
        float4 v3 = Ab[(size_t)(warp + 48) * D4 + off];
        float4 qq = __ldg(&q4[off]);
        acc0 = fmaf(v0.x, qq.x, acc0); acc0 = fmaf(v0.y, qq.y, acc0);
        acc0 = fmaf(v0.z, qq.z, acc0); acc0 = fmaf(v0.w, qq.w, acc0);
        acc1 = fmaf(v1.x, qq.x, acc1); acc1 = fmaf(v1.y, qq.y, acc1);
        acc1 = fmaf(v1.z, qq.z, acc1); acc1 = fmaf(v1.w, qq.w, acc1);
        acc2 = fmaf(v2.x, qq.x, acc2); acc2 = fmaf(v2.y, qq.y, acc2);
        acc2 = fmaf(v2.z, qq.z, acc2); acc2 = fmaf(v2.w, qq.w, acc2);
        acc3 = fmaf(v3.x, qq.x, acc3); acc3 = fmaf(v3.y, qq.y, acc3);
        acc3 = fmaf(v3.z, qq.z, acc3); acc3 = fmaf(v3.w, qq.w, acc3);
    }

    acc0 = warp_sum(acc0);
    acc1 = warp_sum(acc1);
    acc2 = warp_sum(acc2);
    acc3 = warp_sum(acc3);
    if (lane == 0) {
        s_sim[warp +  0] = acc0;
        s_sim[warp + 16] = acc1;
        s_sim[warp + 32] = acc2;
        s_sim[warp + 48] = acc3;
    }
    __syncthreads();

    // ---- Epilogue on warp 0: softmax, KL, NDCG over A=64 (2 answers/lane) ----
    if (warp == 0) {
        const int a0 = lane;
        const int a1 = lane + 32;
        const float si0 = s_sim[a0], si1 = s_sim[a1];
        const float sc0 = s_sc[a0],  sc1 = s_sc[a1];

        // softmax over sim
        float m  = warp_max(fmaxf(si0, si1));
        float e0 = expf(si0 - m), e1 = expf(si1 - m);
        float Z  = warp_sum(e0 + e1);
        float p0 = e0 / Z, p1 = e1 / Z;

        // softmax over target scores (T=1)
        float ms = warp_max(fmaxf(sc0, sc1));
        float t0 = expf(sc0 - ms), t1 = expf(sc1 - ms);
        float Zt = warp_sum(t0 + t1);
        float logZt = logf(Zt);

        // KL(target || pred), reduction = sum over A
        float lt0 = (sc0 - ms) - logZt;              // log target_probs
        float lt1 = (sc1 - ms) - logZt;
        float kl  = (t0 / Zt) * (lt0 - logf(p0 + EPS))
                  + (t1 / Zt) * (lt1 - logf(p1 + EPS));
        kl = warp_sum(kl);

        // ranks (0-indexed), stable tie-break by index == jax stable argsort(-x)
        int r0 = 0, r1 = 0, i0 = 0, i1 = 0;
        #pragma unroll
        for (int j = 0; j < AA; j++) {
            float sj = s_sim[j];
            float cj = s_sc[j];
            r0 += (sj > si0) || (sj == si0 && j < a0);
            r1 += (sj > si1) || (sj == si1 && j < a1);
            i0 += (cj > sc0) || (cj == sc0 && j < a0);
            i1 += (cj > sc1) || (cj == sc1 && j < a1);
        }
        float pred_dcg  = sc0 / log2f((float)(r0 + 2)) + sc1 / log2f((float)(r1 + 2));
        float ideal_dcg = sc0 / log2f((float)(i0 + 2)) + sc1 / log2f((float)(i1 + 2));
        pred_dcg  = warp_sum(pred_dcg);
        ideal_dcg = warp_sum(ideal_dcg);

        if (lane == 0) {
            atomicAdd(&g_kl_sum, kl);
            atomicAdd(&g_ndcg_sum, pred_dcg / (ideal_dcg + EPS));
            __threadfence();  // order our adds before the counter bump
            unsigned int old = atomicAdd(&g_done_count, 1u);
            if (old == BB - 1) {
                // Every other CTA's adds are ordered before its counter bump,
                // and all BB bumps have happened -> sums are complete.
                float klsum = atomicAdd(&g_kl_sum, 0.0f);    // L2 read, L1-safe
                float ndsum = atomicAdd(&g_ndcg_sum, 0.0f);
                out[0] = klsum / (float)BB;                  // loss
                if (out_size > 1) out[1] = ndsum / (float)BB; // avg_ndcg
                // Self-clean for the next graph replay.
                g_kl_sum     = 0.0f;
                g_ndcg_sum   = 0.0f;
                g_done_count = 0u;
            }
        }
    }
}

extern "C" void kernel_launch(void* const* d_in, const int* in_sizes, int n_in,
                              void* d_out, int out_size) {
    const float* q      = (const float*)d_in[0];   // [B, D]
    const float* a_emb  = (const float*)d_in[1];   // [B, A, D]
    const float* scores = (const float*)d_in[2];   // [B, A]
    (void)in_sizes; (void)n_in;
    float* out = (float*)d_out;

    listwise_kernel<<<BB, 512>>>(q, a_emb, scores, out, out_size);
}

// round 9
// speedup vs baseline: 1.0589x; 1.0589x over previous
#include <cuda_runtime.h>
#include <cuda_bf16.h>
#include <math.h>

// Problem constants (fixed by the reference setup_inputs)
#define BB 1024
#define AA 64
#define DD 1024
#define D4 (DD / 4)        // 256 float4 per row
#define EPS 1e-8f

// Device-global accumulators (no allocation allowed). Zero-initialized at
// module load; the last-arriving CTA resets them after finalizing, so every
// graph replay starts from the same state.
__device__ float        g_kl_sum;
__device__ float        g_ndcg_sum;
__device__ unsigned int g_done_count;

__device__ __forceinline__ float warp_sum(float v) {
    #pragma unroll
    for (int o = 16; o > 0; o >>= 1) v += __shfl_xor_sync(0xFFFFFFFFu, v, o);
    return v;
}
__device__ __forceinline__ float warp_max(float v) {
    #pragma unroll
    for (int o = 16; o > 0; o >>= 1) v = fmaxf(v, __shfl_xor_sync(0xFFFFFFFFu, v, o));
    return v;
}

__global__ __launch_bounds__(512, 2)
void listwise_kernel(const float* __restrict__ q,
                     const float* __restrict__ a_emb,
                     const float* __restrict__ scores,
                     float* __restrict__ out,
                     int out_size) {
    const int b    = blockIdx.x;
    const int tid  = threadIdx.x;
    const int warp = tid >> 5;
    const int lane = tid & 31;

    __shared__ float s_q[DD];
    __shared__ float s_sim[AA];
    __shared__ float s_sc[AA];

    // Stage q[b] (4 KB) into smem once, coalesced float4.
    {
        const float4* q4 = reinterpret_cast<const float4*>(q + (size_t)b * DD);
        float4* sq4 = reinterpret_cast<float4*>(s_q);
        if (tid < D4) sq4[tid] = q4[tid];
    }
    if (tid < AA) s_sc[tid] = scores[(size_t)b * AA + tid];
    __syncthreads();

    // Each warp handles answers {warp, warp+16, warp+32, warp+48}.
    // q is re-read from smem each iteration (LDS.128, conflict-free) instead of
    // being register-cached: frees ~32 regs so ptxas can batch more LDG.128s
    // in flight (higher MLP -> higher DRAM utilization).
    const float4* sq4 = reinterpret_cast<const float4*>(s_q);
    const float4* Ab  = reinterpret_cast<const float4*>(a_emb) + (size_t)b * AA * D4;

    float acc0 = 0.f, acc1 = 0.f, acc2 = 0.f, acc3 = 0.f;

    #pragma unroll
    for (int it = 0; it < 8; it++) {
        const int off = it * 32 + lane;
        float4 v0 = Ab[(size_t)(warp +  0) * D4 + off];
        float4 v1 = Ab[(size_t)(warp + 16) * D4 + off];
        float4 v2 = Ab[(size_t)(warp + 32) * D4 + off];
        float4 v3 = Ab[(size_t)(warp + 48) * D4 + off];
        float4 qq = sq4[off];
        acc0 = fmaf(v0.x, qq.x, acc0); acc0 = fmaf(v0.y, qq.y, acc0);
        acc0 = fmaf(v0.z, qq.z, acc0); acc0 = fmaf(v0.w, qq.w, acc0);
        acc1 = fmaf(v1.x, qq.x, acc1); acc1 = fmaf(v1.y, qq.y, acc1);
        acc1 = fmaf(v1.z, qq.z, acc1); acc1 = fmaf(v1.w, qq.w, acc1);
        acc2 = fmaf(v2.x, qq.x, acc2); acc2 = fmaf(v2.y, qq.y, acc2);
        acc2 = fmaf(v2.z, qq.z, acc2); acc2 = fmaf(v2.w, qq.w, acc2);
        acc3 = fmaf(v3.x, qq.x, acc3); acc3 = fmaf(v3.y, qq.y, acc3);
        acc3 = fmaf(v3.z, qq.z, acc3); acc3 = fmaf(v3.w, qq.w, acc3);
    }

    acc0 = warp_sum(acc0);
    acc1 = warp_sum(acc1);
    acc2 = warp_sum(acc2);
    acc3 = warp_sum(acc3);
    if (lane == 0) {
        s_sim[warp +  0] = acc0;
        s_sim[warp + 16] = acc1;
        s_sim[warp + 32] = acc2;
        s_sim[warp + 48] = acc3;
    }
    __syncthreads();

    // ---- Epilogue on warp 0: softmax, KL, NDCG over A=64 (2 answers/lane) ----
    if (warp == 0) {
        const int a0 = lane;
        const int a1 = lane + 32;
        const float si0 = s_sim[a0], si1 = s_sim[a1];
        const float sc0 = s_sc[a0],  sc1 = s_sc[a1];

        // softmax over sim
        float m  = warp_max(fmaxf(si0, si1));
        float e0 = expf(si0 - m), e1 = expf(si1 - m);
        float Z  = warp_sum(e0 + e1);
        float p0 = e0 / Z, p1 = e1 / Z;

        // softmax over target scores (T=1)
        float ms = warp_max(fmaxf(sc0, sc1));
        float t0 = expf(sc0 - ms), t1 = expf(sc1 - ms);
        float Zt = warp_sum(t0 + t1);
        float logZt = logf(Zt);

        // KL(target || pred), reduction = sum over A
        float lt0 = (sc0 - ms) - logZt;              // log target_probs
        float lt1 = (sc1 - ms) - logZt;
        float kl  = (t0 / Zt) * (lt0 - logf(p0 + EPS))
                  + (t1 / Zt) * (lt1 - logf(p1 + EPS));
        kl = warp_sum(kl);

        // ranks (0-indexed), stable tie-break by index == jax stable argsort(-x)
        int r0 = 0, r1 = 0, i0 = 0, i1 = 0;
        #pragma unroll
        for (int j = 0; j < AA; j++) {
            float sj = s_sim[j];
            float cj = s_sc[j];
            r0 += (sj > si0) || (sj == si0 && j < a0);
            r1 += (sj > si1) || (sj == si1 && j < a1);
            i0 += (cj > sc0) || (cj == sc0 && j < a0);
            i1 += (cj > sc1) || (cj == sc1 && j < a1);
        }
        float pred_dcg  = sc0 / log2f((float)(r0 + 2)) + sc1 / log2f((float)(r1 + 2));
        float ideal_dcg = sc0 / log2f((float)(i0 + 2)) + sc1 / log2f((float)(i1 + 2));
        pred_dcg  = warp_sum(pred_dcg);
        ideal_dcg = warp_sum(ideal_dcg);

        if (lane == 0) {
            atomicAdd(&g_kl_sum, kl);
            atomicAdd(&g_ndcg_sum, pred_dcg / (ideal_dcg + EPS));
            __threadfence();  // order our adds before the counter bump
            unsigned int old = atomicAdd(&g_done_count, 1u);
            if (old == BB - 1) {
                // Every other CTA's adds are ordered before its counter bump,
                // and all BB bumps have happened -> sums are complete.
                float klsum = atomicAdd(&g_kl_sum, 0.0f);    // L2 read, L1-safe
                float ndsum = atomicAdd(&g_ndcg_sum, 0.0f);
                out[0] = klsum / (float)BB;                   // loss
                if (out_size > 1) out[1] = ndsum / (float)BB; // avg_ndcg
                // Self-clean for the next graph replay.
                g_kl_sum     = 0.0f;
                g_ndcg_sum   = 0.0f;
                g_done_count = 0u;
            }
        }
    }
}

extern "C" void kernel_launch(void* const* d_in, const int* in_sizes, int n_in,
                              void* d_out, int out_size) {
    const float* q      = (const float*)d_in[0];   // [B, D]
    const float* a_emb  = (const float*)d_in[1];   // [B, A, D]
    const float* scores = (const float*)d_in[2];   // [B, A]
    (void)in_sizes; (void)n_in;
    float* out = (float*)d_out;

    listwise_kernel<<<BB, 512>>>(q, a_emb, scores, out, out_size);
}

// round 11
// speedup vs baseline: 1.0594x; 1.0005x over previous
#include <cuda_runtime.h>
#include <cuda_bf16.h>
#include <math.h>

// Problem constants (fixed by the reference setup_inputs)
#define BB 1024
#define AA 64
#define DD 1024
#define D4 (DD / 4)          // 256 float4 per row
#define EPS 1e-8f

// Pipeline config: each CTA streams its 256 KB row (64 answers x 4 KB)
// through a 4-stage ring of 8 KB stages (2 answers per stage, 32 stages).
#define RING        4
#define STAGE_BYTES 8192
#define STAGE_F4    (STAGE_BYTES / 16)   // 512 float4
#define NSTAGES     32                   // 32 stages x 2 answers = 64 answers

// Device-global accumulators (no allocation allowed). Zero-initialized at
// module load; the last-arriving CTA resets them after finalizing, so every
// graph replay starts from the same state.
__device__ float        g_kl_sum;
__device__ float        g_ndcg_sum;
__device__ unsigned int g_done_count;

__device__ __forceinline__ float warp_sum(float v) {
    #pragma unroll
    for (int o = 16; o > 0; o >>= 1) v += __shfl_xor_sync(0xFFFFFFFFu, v, o);
    return v;
}
__device__ __forceinline__ float warp_max(float v) {
    #pragma unroll
    for (int o = 16; o > 0; o >>= 1) v = fmaxf(v, __shfl_xor_sync(0xFFFFFFFFu, v, o));
    return v;
}

// ---- mbarrier / bulk-async helpers ----
__device__ __forceinline__ unsigned smem_u32(const void* p) {
    return (unsigned)__cvta_generic_to_shared(p);
}
__device__ __forceinline__ void mbar_init(unsigned a, unsigned cnt) {
    asm volatile("mbarrier.init.shared.b64 [%0], %1;" :: "r"(a), "r"(cnt) : "memory");
}
__device__ __forceinline__ void mbar_arrive(unsigned a) {
    asm volatile("mbarrier.arrive.shared.b64 _, [%0];" :: "r"(a) : "memory");
}
__device__ __forceinline__ void mbar_expect_tx(unsigned a, unsigned bytes) {
    asm volatile("mbarrier.arrive.expect_tx.shared.b64 _, [%0], %1;"
                 :: "r"(a), "r"(bytes) : "memory");
}
__device__ __forceinline__ void mbar_wait(unsigned a, unsigned parity) {
    unsigned done;
    asm volatile(
        "{\n\t.reg .pred p;\n\t"
        "mbarrier.try_wait.parity.acquire.cta.shared::cta.b64 p, [%1], %2;\n\t"
        "selp.b32 %0, 1, 0, p;\n\t}"
        : "=r"(done) : "r"(a), "r"(parity) : "memory");
    while (!done) {
        asm volatile(
            "{\n\t.reg .pred p;\n\t"
            "mbarrier.try_wait.parity.acquire.cta.shared::cta.b64 p, [%1], %2, 0x989680;\n\t"
            "selp.b32 %0, 1, 0, p;\n\t}"
            : "=r"(done) : "r"(a), "r"(parity) : "memory");
    }
}
__device__ __forceinline__ void bulk_g2s(unsigned dst, const void* src,
                                         unsigned bytes, unsigned mbar) {
    asm volatile(
        "cp.async.bulk.shared::cta.global.mbarrier::complete_tx::bytes "
        "[%0], [%1], %2, [%3];"
        :: "r"(dst), "l"(src), "r"(bytes), "r"(mbar) : "memory");
}

__global__ __launch_bounds__(512, 2)
void listwise_kernel(const float* __restrict__ q,
                     const float* __restrict__ a_emb,
                     const float* __restrict__ scores,
                     float* __restrict__ out,
                     int out_size) {
    const int b    = blockIdx.x;
    const int tid  = threadIdx.x;
    const int warp = tid >> 5;
    const int lane = tid & 31;

    __shared__ alignas(16) float4 s_buf[RING][STAGE_F4];   // 32 KB ring
    __shared__ float s_q[DD];
    __shared__ float s_sim[AA];
    __shared__ float s_sc[AA];
    __shared__ alignas(8) unsigned long long s_full[RING];
    __shared__ alignas(8) unsigned long long s_empty[RING];

    // Stage q[b] (4 KB) into smem, load scores, zero sim accumulators.
    {
        const float4* q4 = reinterpret_cast<const float4*>(q + (size_t)b * DD);
        float4* sq4 = reinterpret_cast<float4*>(s_q);
        if (tid < D4) sq4[tid] = q4[tid];
    }
    if (tid < AA) {
        s_sc[tid]  = scores[(size_t)b * AA + tid];
        s_sim[tid] = 0.0f;
    }
    if (tid == 0) {
        #pragma unroll
        for (int r = 0; r < RING; r++) {
            mbar_init(smem_u32(&s_full[r]), 1);     // tx-based completion
            mbar_init(smem_u32(&s_empty[r]), 16);   // one arrive per warp
        }
    }
    __syncthreads();

    const char* src = (const char*)(a_emb) + (size_t)b * (AA * DD * sizeof(float));

    // Prologue: fill all RING stages (fresh empty barriers — no wait needed).
    if (tid == 0) {
        #pragma unroll
        for (int r = 0; r < RING; r++) {
            mbar_expect_tx(smem_u32(&s_full[r]), STAGE_BYTES);
            bulk_g2s(smem_u32(&s_buf[r][0]), src + (size_t)r * STAGE_BYTES,
                     STAGE_BYTES, smem_u32(&s_full[r]));
        }
    }

    // Each warp owns a fixed (answer-parity, D-chunk): stage holds 2 answers,
    // warp w computes the partial dot of answer (w&1) over D-chunk (w>>1).
    const int a_local = warp & 1;
    const int chunk   = warp >> 1;              // 0..7, covers 128 floats of D
    const float4 qq = reinterpret_cast<const float4*>(s_q)[chunk * 32 + lane];

    int slot = 0, ph = 0;
    for (int s = 0; s < NSTAGES; s++) {
        mbar_wait(smem_u32(&s_full[slot]), ph);

        float4 v = s_buf[slot][a_local * 256 + chunk * 32 + lane];
        float p = v.x * qq.x;
        p = fmaf(v.y, qq.y, p);
        p = fmaf(v.z, qq.z, p);
        p = fmaf(v.w, qq.w, p);
        p = warp_sum(p);
        if (lane == 0) {
            atomicAdd(&s_sim[2 * s + a_local], p);
            mbar_arrive(smem_u32(&s_empty[slot]));   // stage consumed by this warp
        }

        // Producer (tid 0): refill this slot with stage s+RING once all 16
        // warps have drained it. Producer empty-wait parity == consumer parity
        // for this slot's reuse cycle. Other warps never wait on warp 0
        // (fills always run RING ahead), so the spin here cannot deadlock.
        if (tid == 0) {
            int ns = s + RING;
            if (ns < NSTAGES) {
                mbar_wait(smem_u32(&s_empty[slot]), ph);
                mbar_expect_tx(smem_u32(&s_full[slot]), STAGE_BYTES);
                bulk_g2s(smem_u32(&s_buf[slot][0]), src + (size_t)ns * STAGE_BYTES,
                         STAGE_BYTES, smem_u32(&s_full[slot]));
            }
        }
        if (++slot == RING) { slot = 0; ph ^= 1; }
    }
    __syncthreads();

    // ---- Epilogue on warp 0: softmax, KL, NDCG over A=64 (2 answers/lane) ----
    if (warp == 0) {
        const int a0 = lane;
        const int a1 = lane + 32;
        const float si0 = s_sim[a0], si1 = s_sim[a1];
        const float sc0 = s_sc[a0],  sc1 = s_sc[a1];

        // softmax over sim
        float m  = warp_max(fmaxf(si0, si1));
        float e0 = expf(si0 - m), e1 = expf(si1 - m);
        float Z  = warp_sum(e0 + e1);
        float p0 = e0 / Z, p1 = e1 / Z;

        // softmax over target scores (T=1)
        float ms = warp_max(fmaxf(sc0, sc1));
        float t0 = expf(sc0 - ms), t1 = expf(sc1 - ms);
        float Zt = warp_sum(t0 + t1);
        float logZt = logf(Zt);

        // KL(target || pred), reduction = sum over A
        float lt0 = (sc0 - ms) - logZt;              // log target_probs
        float lt1 = (sc1 - ms) - logZt;
        float kl  = (t0 / Zt) * (lt0 - logf(p0 + EPS))
                  + (t1 / Zt) * (lt1 - logf(p1 + EPS));
        kl = warp_sum(kl);

        // ranks (0-indexed), stable tie-break by index == jax stable argsort(-x)
        int r0 = 0, r1 = 0, i0 = 0, i1 = 0;
        #pragma unroll
        for (int j = 0; j < AA; j++) {
            float sj = s_sim[j];
            float cj = s_sc[j];
            r0 += (sj > si0) || (sj == si0 && j < a0);
            r1 += (sj > si1) || (sj == si1 && j < a1);
            i0 += (cj > sc0) || (cj == sc0 && j < a0);
            i1 += (cj > sc1) || (cj == sc1 && j < a1);
        }
        float pred_dcg  = sc0 / log2f((float)(r0 + 2)) + sc1 / log2f((float)(r1 + 2));
        float ideal_dcg = sc0 / log2f((float)(i0 + 2)) + sc1 / log2f((float)(i1 + 2));
        pred_dcg  = warp_sum(pred_dcg);
        ideal_dcg = warp_sum(ideal_dcg);

        if (lane == 0) {
            atomicAdd(&g_kl_sum, kl);
            atomicAdd(&g_ndcg_sum, pred_dcg / (ideal_dcg + EPS));
            __threadfence();  // order our adds before the counter bump
            unsigned int old = atomicAdd(&g_done_count, 1u);
            if (old == BB - 1) {
                // Every other CTA's adds are ordered before its counter bump,
                // and all BB bumps have happened -> sums are complete.
                float klsum = atomicAdd(&g_kl_sum, 0.0f);    // L2 read, L1-safe
                float ndsum = atomicAdd(&g_ndcg_sum, 0.0f);
                out[0] = klsum / (float)BB;                   // loss
                if (out_size > 1) out[1] = ndsum / (float)BB; // avg_ndcg
                // Self-clean for the next graph replay.
                g_kl_sum     = 0.0f;
                g_ndcg_sum   = 0.0f;
                g_done_count = 0u;
            }
        }
    }
}

extern "C" void kernel_launch(void* const* d_in, const int* in_sizes, int n_in,
                              void* d_out, int out_size) {
    const float* q      = (const float*)d_in[0];   // [B, D]
    const float* a_emb  = (const float*)d_in[1];   // [B, A, D]
    const float* scores = (const float*)d_in[2];   // [B, A]
    (void)in_sizes; (void)n_in;
    float* out = (float*)d_out;

    listwise_kernel<<<BB, 512>>>(q, a_emb, scores, out, out_size);
}

// round 12
// speedup vs baseline: 1.1755x; 1.1095x over previous
#include <cuda_runtime.h>
#include <cuda_bf16.h>
#include <math.h>

// Problem constants (fixed by the reference setup_inputs)
#define BB 1024
#define AA 64
#define DD 1024
#define D4 (DD / 4)          // 256 float4 per row
#define EPS 1e-8f

// Pipeline: each CTA streams its 256 KB row (64 answers x 4 KB) through a
// 2-stage ring of 32 KB stages (8 answers per stage, 8 stages). Big stages
// amortize the ~400-cycle stage-cycle sync cost (R11 lesson).
#define RING         2
#define ANS_PER_STG  8
#define STAGE_BYTES  (ANS_PER_STG * DD * 4)     // 32768
#define STAGE_F4     (STAGE_BYTES / 16)         // 2048 float4
#define NSTAGES      (AA / ANS_PER_STG)         // 8

#define RING_F4      (RING * STAGE_F4)
#define DSMEM_BYTES  (RING * STAGE_BYTES + DD * 4)   // ring + q = 69632

// Device-global accumulators (no allocation allowed). Zero-initialized at
// module load; the last-arriving CTA resets them after finalizing, so every
// graph replay starts from the same state.
__device__ float        g_kl_sum;
__device__ float        g_ndcg_sum;
__device__ unsigned int g_done_count;

__device__ __forceinline__ float warp_sum(float v) {
    #pragma unroll
    for (int o = 16; o > 0; o >>= 1) v += __shfl_xor_sync(0xFFFFFFFFu, v, o);
    return v;
}
__device__ __forceinline__ float warp_max(float v) {
    #pragma unroll
    for (int o = 16; o > 0; o >>= 1) v = fmaxf(v, __shfl_xor_sync(0xFFFFFFFFu, v, o));
    return v;
}

// ---- mbarrier / bulk-async helpers ----
__device__ __forceinline__ unsigned smem_u32(const void* p) {
    return (unsigned)__cvta_generic_to_shared(p);
}
__device__ __forceinline__ void mbar_init(unsigned a, unsigned cnt) {
    asm volatile("mbarrier.init.shared.b64 [%0], %1;" :: "r"(a), "r"(cnt) : "memory");
}
__device__ __forceinline__ void mbar_arrive(unsigned a) {
    asm volatile("mbarrier.arrive.shared.b64 _, [%0];" :: "r"(a) : "memory");
}
__device__ __forceinline__ void mbar_expect_tx(unsigned a, unsigned bytes) {
    asm volatile("mbarrier.arrive.expect_tx.shared.b64 _, [%0], %1;"
                 :: "r"(a), "r"(bytes) : "memory");
}
__device__ __forceinline__ void mbar_wait(unsigned a, unsigned parity) {
    unsigned done;
    asm volatile(
        "{\n\t.reg .pred p;\n\t"
        "mbarrier.try_wait.parity.acquire.cta.shared::cta.b64 p, [%1], %2;\n\t"
        "selp.b32 %0, 1, 0, p;\n\t}"
        : "=r"(done) : "r"(a), "r"(parity) : "memory");
    while (!done) {
        asm volatile(
            "{\n\t.reg .pred p;\n\t"
            "mbarrier.try_wait.parity.acquire.cta.shared::cta.b64 p, [%1], %2, 0x989680;\n\t"
            "selp.b32 %0, 1, 0, p;\n\t}"
            : "=r"(done) : "r"(a), "r"(parity) : "memory");
    }
}
__device__ __forceinline__ void bulk_g2s(unsigned dst, const void* src,
                                         unsigned bytes, unsigned mbar) {
    asm volatile(
        "cp.async.bulk.shared::cta.global.mbarrier::complete_tx::bytes "
        "[%0], [%1], %2, [%3];"
        :: "r"(dst), "l"(src), "r"(bytes), "r"(mbar) : "memory");
}

__global__ __launch_bounds__(512, 3)
void listwise_kernel(const float* __restrict__ q,
                     const float* __restrict__ a_emb,
                     const float* __restrict__ scores,
                     float* __restrict__ out,
                     int out_size) {
    const int b    = blockIdx.x;
    const int tid  = threadIdx.x;
    const int warp = tid >> 5;
    const int lane = tid & 31;

    extern __shared__ __align__(16) float4 dyn[];
    float4* s_buf = dyn;                                    // [RING_F4] ring
    float4* s_q4  = dyn + RING_F4;                          // [D4] q row

    __shared__ float s_part[AA][2];    // per-answer half-dot partials
    __shared__ float s_sim[AA];
    __shared__ float s_sc[AA];
    __shared__ alignas(8) unsigned long long s_full[RING];
    __shared__ alignas(8) unsigned long long s_empty[RING];

    // Stage q[b] (4 KB) into smem once, coalesced float4; scores; barriers.
    {
        const float4* q4 = reinterpret_cast<const float4*>(q + (size_t)b * DD);
        if (tid < D4) s_q4[tid] = q4[tid];
    }
    if (tid < AA) s_sc[tid] = scores[(size_t)b * AA + tid];
    if (tid == 0) {
        #pragma unroll
        for (int r = 0; r < RING; r++) {
            mbar_init(smem_u32(&s_full[r]), 1);     // tx-based completion
            mbar_init(smem_u32(&s_empty[r]), 16);   // one arrive per warp
        }
    }
    __syncthreads();

    const char* src = (const char*)(a_emb) + (size_t)b * (AA * DD * sizeof(float));

    // Prologue: fill both ring slots (fresh empty barriers — no wait needed).
    if (tid == 0) {
        #pragma unroll
        for (int r = 0; r < RING; r++) {
            mbar_expect_tx(smem_u32(&s_full[r]), STAGE_BYTES);
            bulk_g2s(smem_u32(&s_buf[(size_t)r * STAGE_F4]),
                     src + (size_t)r * STAGE_BYTES,
                     STAGE_BYTES, smem_u32(&s_full[r]));
        }
    }

    // Warp w owns (answer w&7, D-half w>>3) within each stage.
    // Preload this warp's q half-slice (4 float4 = 16 regs), reused 8 stages.
    const int a_local = warp & 7;
    const int half    = warp >> 3;            // 0..1, 512 floats each
    float4 qq[4];
    #pragma unroll
    for (int i = 0; i < 4; i++) qq[i] = s_q4[half * 128 + i * 32 + lane];

    const int voff = a_local * 256 + half * 128 + lane;   // float4 idx in stage

    for (int s = 0; s < NSTAGES; s++) {
        const int slot = s & 1;
        const int fp   = (s >> 1) & 1;

        mbar_wait(smem_u32(&s_full[slot]), fp);

        const float4* vbase = s_buf + (size_t)slot * STAGE_F4 + voff;
        float p = 0.f;
        #pragma unroll
        for (int i = 0; i < 4; i++) {
            float4 v = vbase[i * 32];
            p = fmaf(v.x, qq[i].x, p);
            p = fmaf(v.y, qq[i].y, p);
            p = fmaf(v.z, qq[i].z, p);
            p = fmaf(v.w, qq[i].w, p);
        }
        p = warp_sum(p);
        if (lane == 0) {
            s_part[s * ANS_PER_STG + a_local][half] = p;   // unique writer
            mbar_arrive(smem_u32(&s_empty[slot]));         // stage consumed
        }

        // Producer (tid 0): refill this slot with stage s+RING once all 16
        // warps have drained it. Empty-drain #u satisfies parity u&1 = fp.
        // Fills always run RING ahead of consumption, so no deadlock.
        if (tid == 0) {
            int ns = s + RING;
            if (ns < NSTAGES) {
                mbar_wait(smem_u32(&s_empty[slot]), fp);
                mbar_expect_tx(smem_u32(&s_full[slot]), STAGE_BYTES);
                bulk_g2s(smem_u32(&s_buf[(size_t)slot * STAGE_F4]),
                         src + (size_t)ns * STAGE_BYTES,
                         STAGE_BYTES, smem_u32(&s_full[slot]));
            }
        }
    }
    __syncthreads();

    // ---- Epilogue on warp 0: softmax, KL, NDCG over A=64 (2 answers/lane) ----
    if (warp == 0) {
        const int a0 = lane;
        const int a1 = lane + 32;
        const float si0 = s_part[a0][0] + s_part[a0][1];
        const float si1 = s_part[a1][0] + s_part[a1][1];
        const float sc0 = s_sc[a0],  sc1 = s_sc[a1];
        s_sim[a0] = si0;
        s_sim[a1] = si1;
        __syncwarp();

        // softmax over sim
        float m  = warp_max(fmaxf(si0, si1));
        float e0 = expf(si0 - m), e1 = expf(si1 - m);
        float Z  = warp_sum(e0 + e1);
        float p0 = e0 / Z, p1 = e1 / Z;

        // softmax over target scores (T=1)
        float ms = warp_max(fmaxf(sc0, sc1));
        float t0 = expf(sc0 - ms), t1 = expf(sc1 - ms);
        float Zt = warp_sum(t0 + t1);
        float logZt = logf(Zt);

        // KL(target || pred), reduction = sum over A
        float lt0 = (sc0 - ms) - logZt;              // log target_probs
        float lt1 = (sc1 - ms) - logZt;
        float kl  = (t0 / Zt) * (lt0 - logf(p0 + EPS))
                  + (t1 / Zt) * (lt1 - logf(p1 + EPS));
        kl = warp_sum(kl);

        // ranks (0-indexed), stable tie-break by index == jax stable argsort(-x)
        int r0 = 0, r1 = 0, i0 = 0, i1 = 0;
        #pragma unroll
        for (int j = 0; j < AA; j++) {
            float sj = s_sim[j];
            float cj = s_sc[j];
            r0 += (sj > si0) || (sj == si0 && j < a0);
            r1 += (sj > si1) || (sj == si1 && j < a1);
            i0 += (cj > sc0) || (cj == sc0 && j < a0);
            i1 += (cj > sc1) || (cj == sc1 && j < a1);
        }
        float pred_dcg  = sc0 / log2f((float)(r0 + 2)) + sc1 / log2f((float)(r1 + 2));
        float ideal_dcg = sc0 / log2f((float)(i0 + 2)) + sc1 / log2f((float)(i1 + 2));
        pred_dcg  = warp_sum(pred_dcg);
        ideal_dcg = warp_sum(ideal_dcg);

        if (lane == 0) {
            atomicAdd(&g_kl_sum, kl);
            atomicAdd(&g_ndcg_sum, pred_dcg / (ideal_dcg + EPS));
            __threadfence();  // order our adds before the counter bump
            unsigned int old = atomicAdd(&g_done_count, 1u);
            if (old == BB - 1) {
                // Every other CTA's adds are ordered before its counter bump,
                // and all BB bumps have happened -> sums are complete.
                float klsum = atomicAdd(&g_kl_sum, 0.0f);    // L2 read, L1-safe
                float ndsum = atomicAdd(&g_ndcg_sum, 0.0f);
                out[0] = klsum / (float)BB;                   // loss
                if (out_size > 1) out[1] = ndsum / (float)BB; // avg_ndcg
                // Self-clean for the next graph replay.
                g_kl_sum     = 0.0f;
                g_ndcg_sum   = 0.0f;
                g_done_count = 0u;
            }
        }
    }
}

extern "C" void kernel_launch(void* const* d_in, const int* in_sizes, int n_in,
                              void* d_out, int out_size) {
    const float* q      = (const float*)d_in[0];   // [B, D]
    const float* a_emb  = (const float*)d_in[1];   // [B, A, D]
    const float* scores = (const float*)d_in[2];   // [B, A]
    (void)in_sizes; (void)n_in;
    float* out = (float*)d_out;

    // Dynamic smem > 48 KB static limit; host attribute call, graph-capture
    // safe (not a stream op), idempotent every launch.
    cudaFuncSetAttribute(listwise_kernel,
                         cudaFuncAttributeMaxDynamicSharedMemorySize,
                         DSMEM_BYTES);

    listwise_kernel<<<BB, 512, DSMEM_BYTES>>>(q, a_emb, scores, out, out_size);
}